// round 17
// baseline (speedup 1.0000x reference)
#include <cuda_runtime.h>
#include <cuda_fp16.h>
#include <cstdint>

// ---------------- Problem constants ----------------
#define T_STEPS 512
#define BATCH   256
#define INPUT_  256
#define HID_    64
#define GATES_  256            // 4*HID
#define OUT_    1024
#define M_ROWS  (T_STEPS * BATCH)          // 131072
#define OUT_ELEMS ((size_t)M_ROWS * OUT_)
#define HC_ELEMS  (BATCH * HID_)

// Scratch (allocation-free rule: __device__ globals)
__device__ float  g_xg[(size_t)M_ROWS * GATES_];    // gate pre-activations (fp32)
__device__ __half g_hs_h[(size_t)M_ROWS * HID_];    // hidden states as fp16
__device__ __half g_wih_hi[GATES_ * INPUT_];        // W_ih split-2 fp16
__device__ __half g_wih_lo[GATES_ * INPUT_];
__device__ __half g_wout_h[OUT_ * HID_];            // W_out fp16

// ---------------- helpers ----------------
__device__ __forceinline__ uint32_t smem_u32(const void* p) {
    uint32_t a;
    asm("{ .reg .u64 t; cvta.to.shared.u64 t, %1; cvt.u32.u64 %0, t; }"
        : "=r"(a) : "l"(p));
    return a;
}
__device__ __forceinline__ float tanh_fast(float x) {
    float y;
    asm("tanh.approx.f32 %0, %1;" : "=f"(y) : "f"(x));
    return y;
}
__device__ __forceinline__ float sigm(float x) {   // 1 MUFU
    return 0.5f * tanh_fast(0.5f * x) + 0.5f;
}

// Plain-target tensor / async-copy PTX (sm_80+ features only).
#define LDMX4(r, addr) \
    asm volatile("ldmatrix.sync.aligned.m8n8.x4.shared.b16 {%0,%1,%2,%3}, [%4];" \
        : "=r"((r)[0]), "=r"((r)[1]), "=r"((r)[2]), "=r"((r)[3]) : "r"(addr))

#define MMA16816(d, a, b) \
    asm volatile("mma.sync.aligned.m16n8k16.row.col.f32.f16.f16.f32 " \
        "{%0,%1,%2,%3}, {%4,%5,%6,%7}, {%8,%9}, {%0,%1,%2,%3};" \
        : "+f"((d)[0]), "+f"((d)[1]), "+f"((d)[2]), "+f"((d)[3]) \
        : "r"((a)[0]), "r"((a)[1]), "r"((a)[2]), "r"((a)[3]), \
          "r"((b)[0]), "r"((b)[1]))

#define CPA16(dst, src) \
    asm volatile("cp.async.cg.shared.global [%0], [%1], 16;" \
                 :: "r"(dst), "l"(src) : "memory")
#define CPA_COMMIT() asm volatile("cp.async.commit_group;" ::: "memory")
#define CPA_WAIT0()  asm volatile("cp.async.wait_group 0;" ::: "memory")

// ---------------- f32x2 packed-FMA helpers (LSTM) ----------------
__device__ __forceinline__ unsigned long long pk(float x, float y) {
    unsigned long long r;
    asm("mov.b64 %0, {%1, %2};" : "=l"(r) : "f"(x), "f"(y));
    return r;
}
__device__ __forceinline__ void fma2(unsigned long long& d,
                                     unsigned long long a, unsigned long long b) {
    asm("fma.rn.f32x2 %0, %1, %2, %0;" : "+l"(d) : "l"(a), "l"(b));
}
__device__ __forceinline__ float2 upk(unsigned long long v) {
    float2 r;
    asm("mov.b64 {%0, %1}, %2;" : "=f"(r.x), "=f"(r.y) : "l"(v));
    return r;
}

// ---------------- weight conversion kernels ----------------
__global__ void __launch_bounds__(256)
k_cvt_h(const float* __restrict__ src, __half* __restrict__ dst, int n8) {
    int i = blockIdx.x * 256 + threadIdx.x;
    if (i >= n8) return;
    size_t idx = (size_t)i * 8;
    float4 a = *(const float4*)(src + idx);
    float4 b = *(const float4*)(src + idx + 4);
    uint4 o;
    __half2* op = (__half2*)&o;
    op[0] = __floats2half2_rn(a.x, a.y);
    op[1] = __floats2half2_rn(a.z, a.w);
    op[2] = __floats2half2_rn(b.x, b.y);
    op[3] = __floats2half2_rn(b.z, b.w);
    *(uint4*)(dst + idx) = o;
}
__global__ void __launch_bounds__(256)
k_split_h(const float* __restrict__ src, __half* __restrict__ hi,
          __half* __restrict__ lo, int n4) {
    int i = blockIdx.x * 256 + threadIdx.x;
    if (i >= n4) return;
    size_t idx = (size_t)i * 4;
    float4 a = *(const float4*)(src + idx);
    float f[4] = {a.x, a.y, a.z, a.w};
    __half h[4], l[4];
#pragma unroll
    for (int q = 0; q < 4; q++) {
        h[q] = __float2half_rn(f[q]);
        l[q] = __float2half_rn(f[q] - __half2float(h[q]));
    }
    *(uint2*)(hi + idx) = *(uint2*)h;
    *(uint2*)(lo + idx) = *(uint2*)l;
}

// ---------------- shared GEMM geometry ----------------
// CTA tile 128x128, BK=32, 8 warps as 2(M) x 4(N); warp tile 64x32.
// Smem tile: 128 rows x 80 B (conflict-free ldmatrix via 20-bank row rotation).
#define SM_LDR 80
#define TILE_B (128 * SM_LDR)
#define XG_SMEM  (6 * TILE_B)   // 2 stages x (A + Bhi + Blo)
#define OUT_SMEM (4 * TILE_B)   // 2 stages x (A + B)

// ---------------- K1: xg = x @ W_ih^T + (b_ih+b_hh) ----------------
// A = x fp32 (converted in-kernel), B = W_ih split-2 fp16 via cp.async.
__global__ void __launch_bounds__(256, 2)
k_xg_mma(const float* __restrict__ x, const float* __restrict__ bih,
         const float* __restrict__ bhh) {
    extern __shared__ char dsm[];
    const uint32_t smBase = smem_u32(dsm);
    constexpr int K = INPUT_;
    const int m0 = blockIdx.y * 128, n0 = blockIdx.x * 128;

    const int tid  = threadIdx.x;
    const int lane = tid & 31;
    const int warp = tid >> 5;
    const int wm = (warp & 1) * 64;
    const int wn = (warp >> 1) * 32;

    float acc[4][4][4];
#pragma unroll
    for (int i = 0; i < 4; i++)
#pragma unroll
        for (int j = 0; j < 4; j++)
#pragma unroll
            for (int q = 0; q < 4; q++) acc[i][j][q] = 0.0f;

    const int lrow = tid >> 1;         // 0..127
    const int lc16 = (tid & 1) * 2;    // 16B-chunk pair {0,1} or {2,3}

    const uint32_t aoff = (uint32_t)((wm + (lane & 15)) * SM_LDR + (lane >> 4) * 16);
    const uint32_t boff = (uint32_t)((wn + (lane & 7) + ((lane >> 4) & 1) * 8) * SM_LDR
                                     + ((lane >> 3) & 1) * 16);

    const float* ap   = x + (size_t)(m0 + lrow) * K + lc16 * 8;
    const size_t brow = (size_t)(n0 + lrow) * K;

    float4 ar[4];
#define LDA(kt)                                                 \
    do {                                                        \
        ar[0] = *(const float4*)(ap + (kt));                    \
        ar[1] = *(const float4*)(ap + (kt) + 4);                \
        ar[2] = *(const float4*)(ap + (kt) + 8);                \
        ar[3] = *(const float4*)(ap + (kt) + 12);               \
    } while (0)
#define STA(stage)                                                              \
    do {                                                                        \
        _Pragma("unroll")                                                       \
        for (int c = 0; c < 2; c++) {                                           \
            __half2 h[4];                                                       \
            float4 lo = ar[2 * c], hi = ar[2 * c + 1];                          \
            h[0] = __floats2half2_rn(lo.x, lo.y);                               \
            h[1] = __floats2half2_rn(lo.z, lo.w);                               \
            h[2] = __floats2half2_rn(hi.x, hi.y);                               \
            h[3] = __floats2half2_rn(hi.z, hi.w);                               \
            *(uint4*)(dsm + (stage) * (3 * TILE_B) + lrow * SM_LDR              \
                      + (lc16 + c) * 16) = *(uint4*)h;                          \
        }                                                                       \
    } while (0)
#define LDB(stage, kt)                                                          \
    do {                                                                        \
        _Pragma("unroll")                                                       \
        for (int c = 0; c < 2; c++) {                                           \
            uint32_t d = smBase + (stage) * (3 * TILE_B)                        \
                         + lrow * SM_LDR + (lc16 + c) * 16;                     \
            CPA16(d + TILE_B,     g_wih_hi + brow + (kt) + (lc16 + c) * 8);     \
            CPA16(d + 2 * TILE_B, g_wih_lo + brow + (kt) + (lc16 + c) * 8);     \
        }                                                                       \
    } while (0)

    // Preamble: stage 0 (A converted + B cp.async), prefetch A(kt=32)
    LDA(0);
    STA(0);
    LDB(0, 0);
    CPA_COMMIT();
    LDA(32);

    int cur = 0;
    for (int kt = 0; kt < K; kt += 32, cur ^= 1) {
        const bool more = (kt + 32 < K);
        CPA_WAIT0();
        __syncthreads();   // stage cur B ready; all prior reads of stage nxt done
        if (more) {
            LDB(cur ^ 1, kt + 32);   // safe: nxt's readers finished before barrier
            CPA_COMMIT();
        }

        const uint32_t aT  = smBase + cur * (3 * TILE_B);
        const uint32_t bhT = aT + TILE_B;
        const uint32_t blT = aT + 2 * TILE_B;
#pragma unroll
        for (int k16 = 0; k16 < 2; k16++) {
            uint32_t bh[4][2], bl[4][2];
#pragma unroll
            for (int njp = 0; njp < 2; njp++) {
                uint32_t th[4], tl[4];
                uint32_t d = boff + njp * (16 * SM_LDR) + k16 * 32;
                LDMX4(th, bhT + d);
                LDMX4(tl, blT + d);
                bh[2 * njp][0] = th[0]; bh[2 * njp][1] = th[1];
                bh[2 * njp + 1][0] = th[2]; bh[2 * njp + 1][1] = th[3];
                bl[2 * njp][0] = tl[0]; bl[2 * njp][1] = tl[1];
                bl[2 * njp + 1][0] = tl[2]; bl[2 * njp + 1][1] = tl[3];
            }
#pragma unroll
            for (int mi = 0; mi < 4; mi++) {
                uint32_t ah[4];
                LDMX4(ah, aT + aoff + mi * (16 * SM_LDR) + k16 * 32);
#pragma unroll
                for (int nj = 0; nj < 4; nj++) {
                    MMA16816(acc[mi][nj], ah, bh[nj]);
                    MMA16816(acc[mi][nj], ah, bl[nj]);
                }
            }
        }

        if (more) {
            STA(cur ^ 1);                     // nxt A-tile: readers done pre-barrier
            if (kt + 64 < K) LDA(kt + 64);
        }
    }
#undef LDA
#undef STA
#undef LDB

    // Epilogue -> g_xg (fp32, no activation)
    const int er = lane >> 2;
    const int ec = (lane & 3) * 2;
#pragma unroll
    for (int nj = 0; nj < 4; nj++) {
        int n = n0 + wn + nj * 8 + ec;
        float bb0 = bih[n]     + bhh[n];
        float bb1 = bih[n + 1] + bhh[n + 1];
#pragma unroll
        for (int mi = 0; mi < 4; mi++) {
            int r0 = m0 + wm + mi * 16 + er;
            *(float2*)(g_xg + (size_t)r0 * GATES_ + n) =
                make_float2(acc[mi][nj][0] + bb0, acc[mi][nj][1] + bb1);
            *(float2*)(g_xg + (size_t)(r0 + 8) * GATES_ + n) =
                make_float2(acc[mi][nj][2] + bb0, acc[mi][nj][3] + bb1);
        }
    }
}

// ---------------- K3: out = sigmoid(hs @ W_out^T + b_out) ----------------
__global__ void __launch_bounds__(256, 2)
k_out_mma(const float* __restrict__ bout, float* __restrict__ out) {
    extern __shared__ char dsm[];
    const uint32_t smBase = smem_u32(dsm);
    constexpr int K = HID_;
    const int m0 = blockIdx.y * 128, n0 = blockIdx.x * 128;

    const int tid  = threadIdx.x;
    const int lane = tid & 31;
    const int warp = tid >> 5;
    const int wm = (warp & 1) * 64;
    const int wn = (warp >> 1) * 32;

    float acc[4][4][4];
#pragma unroll
    for (int i = 0; i < 4; i++)
#pragma unroll
        for (int j = 0; j < 4; j++)
#pragma unroll
            for (int q = 0; q < 4; q++) acc[i][j][q] = 0.0f;

    const int lrow = tid >> 1;
    const int lc16 = (tid & 1) * 2;

    const uint32_t aoff = (uint32_t)((wm + (lane & 15)) * SM_LDR + (lane >> 4) * 16);
    const uint32_t boff = (uint32_t)((wn + (lane & 7) + ((lane >> 4) & 1) * 8) * SM_LDR
                                     + ((lane >> 3) & 1) * 16);

    const size_t arow = (size_t)(m0 + lrow) * K;
    const size_t brow = (size_t)(n0 + lrow) * K;

#define LDAB(stage, kt)                                                         \
    do {                                                                        \
        _Pragma("unroll")                                                       \
        for (int c = 0; c < 2; c++) {                                           \
            uint32_t d = smBase + (stage) * (2 * TILE_B)                        \
                         + lrow * SM_LDR + (lc16 + c) * 16;                     \
            CPA16(d,          g_hs_h  + arow + (kt) + (lc16 + c) * 8);          \
            CPA16(d + TILE_B, g_wout_h + brow + (kt) + (lc16 + c) * 8);         \
        }                                                                       \
    } while (0)

    LDAB(0, 0);
    CPA_COMMIT();

    int cur = 0;
    for (int kt = 0; kt < K; kt += 32, cur ^= 1) {
        const bool more = (kt + 32 < K);
        CPA_WAIT0();
        __syncthreads();
        if (more) {
            LDAB(cur ^ 1, kt + 32);
            CPA_COMMIT();
        }
        const uint32_t aT = smBase + cur * (2 * TILE_B);
        const uint32_t bT = aT + TILE_B;
#pragma unroll
        for (int k16 = 0; k16 < 2; k16++) {
            uint32_t bh[4][2];
#pragma unroll
            for (int njp = 0; njp < 2; njp++) {
                uint32_t th[4];
                LDMX4(th, bT + boff + njp * (16 * SM_LDR) + k16 * 32);
                bh[2 * njp][0] = th[0]; bh[2 * njp][1] = th[1];
                bh[2 * njp + 1][0] = th[2]; bh[2 * njp + 1][1] = th[3];
            }
#pragma unroll
            for (int mi = 0; mi < 4; mi++) {
                uint32_t ah[4];
                LDMX4(ah, aT + aoff + mi * (16 * SM_LDR) + k16 * 32);
#pragma unroll
                for (int nj = 0; nj < 4; nj++) MMA16816(acc[mi][nj], ah, bh[nj]);
            }
        }
    }
#undef LDAB

    // Epilogue: 1-MUFU sigmoid (R15-validated error profile)
    const int er = lane >> 2;
    const int ec = (lane & 3) * 2;
#pragma unroll
    for (int nj = 0; nj < 4; nj++) {
        int n = n0 + wn + nj * 8 + ec;
        float bb0 = bout[n];
        float bb1 = bout[n + 1];
#pragma unroll
        for (int mi = 0; mi < 4; mi++) {
            int r0 = m0 + wm + mi * 16 + er;
            *(float2*)(out + (size_t)r0 * OUT_ + n) =
                make_float2(sigm(acc[mi][nj][0] + bb0), sigm(acc[mi][nj][1] + bb1));
            *(float2*)(out + (size_t)(r0 + 8) * OUT_ + n) =
                make_float2(sigm(acc[mi][nj][2] + bb0), sigm(acc[mi][nj][3] + bb1));
        }
    }
}

// ---------------- K2: LSTM recurrence (2 batches/CTA, grid=128) -------------
// 1 CTA per SM (no inter-CTA arbitration). Thread tid owns gate row `row` of
// W_hh for BOTH batches (weights reused); two independent dependency chains.
// lane = gate*8 + jj (gate order i,f,g,o), j = warp*8 + jj.
__global__ void __launch_bounds__(256, 1)
k_lstm(const float* __restrict__ h0, const float* __restrict__ c0,
       const float* __restrict__ Whh,
       float* __restrict__ hT, float* __restrict__ cT) {
    const int b0   = blockIdx.x * 2;
    const int b1   = b0 + 1;
    const int tid  = threadIdx.x;
    const int lane = tid & 31;
    const int w    = tid >> 5;
    const int gate = lane >> 3;
    const int jj   = lane & 7;
    const int j    = w * 8 + jj;
    const int row  = gate * HID_ + j;

    unsigned long long w2[32];
    const float4* wr = (const float4*)(Whh + row * HID_);
#pragma unroll
    for (int q = 0; q < 16; q++) {
        float4 v = wr[q];
        w2[2 * q]     = pk(v.x, v.y);
        w2[2 * q + 1] = pk(v.z, v.w);
    }

    __shared__ __align__(16) float hb[2][2][HID_];   // [phase][batch][hid]
    if (tid < HID_) {
        hb[0][0][tid] = h0[b0 * HID_ + tid];
        hb[0][1][tid] = h0[b1 * HID_ + tid];
    }
    float cA = c0[b0 * HID_ + j];
    float cB = c0[b1 * HID_ + j];
    float hA = 0.0f, hB = 0.0f;
    __syncthreads();

    const float* xpA = g_xg + (size_t)b0 * GATES_ + row;
    const float* xpB = g_xg + (size_t)b1 * GATES_ + row;
    int p = 0;

#define XLDA(tq) (((tq) < T_STEPS) ? xpA[(size_t)(tq) * (BATCH * GATES_)] : 0.0f)
#define XLDB(tq) (((tq) < T_STEPS) ? xpB[(size_t)(tq) * (BATCH * GATES_)] : 0.0f)

#define LSTM_STEP2(XA, XB, T)                                                   \
    do {                                                                        \
        unsigned long long a0 = 0, a1 = 0, a2 = 0, a3 = 0;                      \
        unsigned long long d0 = 0, d1 = 0, d2 = 0, d3 = 0;                      \
        const ulonglong2* hpA = (const ulonglong2*)hb[p][0];                    \
        const ulonglong2* hpB = (const ulonglong2*)hb[p][1];                    \
        _Pragma("unroll")                                                       \
        for (int q = 0; q < 8; q++) {                                           \
            ulonglong2 hA2 = hpA[2 * q], hA3 = hpA[2 * q + 1];                  \
            ulonglong2 hB2 = hpB[2 * q], hB3 = hpB[2 * q + 1];                  \
            fma2(a0, w2[4 * q],     hA2.x);                                     \
            fma2(d0, w2[4 * q],     hB2.x);                                     \
            fma2(a1, w2[4 * q + 1], hA2.y);                                     \
            fma2(d1, w2[4 * q + 1], hB2.y);                                     \
            fma2(a2, w2[4 * q + 2], hA3.x);                                     \
            fma2(d2, w2[4 * q + 2], hB3.x);                                     \
            fma2(a3, w2[4 * q + 3], hA3.y);                                     \
            fma2(d3, w2[4 * q + 3], hB3.y);                                     \
        }                                                                       \
        float2 sa0 = upk(a0), sa1 = upk(a1), sa2 = upk(a2), sa3 = upk(a3);      \
        float2 sb0 = upk(d0), sb1 = upk(d1), sb2 = upk(d2), sb3 = upk(d3);      \
        float sA = (XA) + (((sa0.x + sa0.y) + (sa1.x + sa1.y)) +                \
                           ((sa2.x + sa2.y) + (sa3.x + sa3.y)));                \
        float sB = (XB) + (((sb0.x + sb0.y) + (sb1.x + sb1.y)) +                \
                           ((sb2.x + sb2.y) + (sb3.x + sb3.y)));                \
        float aA = (gate == 2) ? tanh_fast(sA) : sigm(sA);                      \
        float aB = (gate == 2) ? tanh_fast(sB) : sigm(sB);                      \
        float iA = __shfl_sync(0xffffffffu, aA, jj);                            \
        float iB = __shfl_sync(0xffffffffu, aB, jj);                            \
        float fA = __shfl_sync(0xffffffffu, aA, 8 + jj);                        \
        float fB = __shfl_sync(0xffffffffu, aB, 8 + jj);                        \
        float gA = __shfl_sync(0xffffffffu, aA, 16 + jj);                       \
        float gB = __shfl_sync(0xffffffffu, aB, 16 + jj);                       \
        float oA = __shfl_sync(0xffffffffu, aA, 24 + jj);                       \
        float oB = __shfl_sync(0xffffffffu, aB, 24 + jj);                       \
        cA = fA * cA + iA * gA;                                                 \
        cB = fB * cB + iB * gB;                                                 \
        hA = oA * tanh_fast(cA);                                                \
        hB = oB * tanh_fast(cB);                                                \
        if (gate == 0) {                                                        \
            hb[p ^ 1][0][j] = hA;                                               \
            hb[p ^ 1][1][j] = hB;                                               \
            g_hs_h[((size_t)(T) * BATCH + b0) * HID_ + j] = __float2half(hA);   \
            g_hs_h[((size_t)(T) * BATCH + b1) * HID_ + j] = __float2half(hB);   \
        }                                                                       \
        __syncthreads();                                                        \
        p ^= 1;                                                                 \
    } while (0)

    float xa0 = XLDA(0), xa1 = XLDA(1), xa2 = XLDA(2), xa3 = XLDA(3);
    float xb0 = XLDB(0), xb1 = XLDB(1), xb2 = XLDB(2), xb3 = XLDB(3);
    for (int t = 0; t < T_STEPS; t += 4) {
        float na0 = XLDA(t + 4), na1 = XLDA(t + 5), na2 = XLDA(t + 6), na3 = XLDA(t + 7);
        float nb0 = XLDB(t + 4), nb1 = XLDB(t + 5), nb2 = XLDB(t + 6), nb3 = XLDB(t + 7);
        LSTM_STEP2(xa0, xb0, t);
        LSTM_STEP2(xa1, xb1, t + 1);
        LSTM_STEP2(xa2, xb2, t + 2);
        LSTM_STEP2(xa3, xb3, t + 3);
        xa0 = na0; xa1 = na1; xa2 = na2; xa3 = na3;
        xb0 = nb0; xb1 = nb1; xb2 = nb2; xb3 = nb3;
    }

    if (gate == 0) {
        hT[b0 * HID_ + j] = hA;
        cT[b0 * HID_ + j] = cA;
        hT[b1 * HID_ + j] = hB;
        cT[b1 * HID_ + j] = cB;
    }
#undef LSTM_STEP2
#undef XLDA
#undef XLDB
}

extern "C" void kernel_launch(void* const* d_in, const int* in_sizes, int n_in,
                              void* d_out, int out_size) {
    const float* x    = (const float*)d_in[0];
    const float* h0   = (const float*)d_in[1];
    const float* c0   = (const float*)d_in[2];
    const float* Wih  = (const float*)d_in[3];
    const float* Whh  = (const float*)d_in[4];
    const float* bih  = (const float*)d_in[5];
    const float* bhh  = (const float*)d_in[6];
    const float* Wout = (const float*)d_in[7];
    const float* bout = (const float*)d_in[8];

    float* out = (float*)d_out;
    float* hT  = out + OUT_ELEMS;
    float* cT  = hT + HC_ELEMS;

    cudaFuncSetAttribute(k_xg_mma, cudaFuncAttributeMaxDynamicSharedMemorySize, XG_SMEM);
    cudaFuncSetAttribute(k_out_mma, cudaFuncAttributeMaxDynamicSharedMemorySize, OUT_SMEM);

    __half *wih_h, *wih_l, *wout_h;
    cudaGetSymbolAddress((void**)&wih_h, g_wih_hi);
    cudaGetSymbolAddress((void**)&wih_l, g_wih_lo);
    cudaGetSymbolAddress((void**)&wout_h, g_wout_h);

    // 0) weight conversions (tiny)
    k_split_h<<<(GATES_ * INPUT_ / 4 + 255) / 256, 256>>>(Wih, wih_h, wih_l,
                                                          GATES_ * INPUT_ / 4);
    k_cvt_h<<<(OUT_ * HID_ / 8 + 255) / 256, 256>>>(Wout, wout_h, OUT_ * HID_ / 8);

    // 1) xg = x @ W_ih^T + (b_ih + b_hh)  — fused A cvt, split-2 W
    k_xg_mma<<<dim3(GATES_ / 128, M_ROWS / 128), 256, XG_SMEM>>>(x, bih, bhh);
    // 2) sequential LSTM recurrence — 2 batches/CTA, 1 CTA/SM
    k_lstm<<<BATCH / 2, 256>>>(h0, c0, Whh, hT, cT);
    // 3) out = sigmoid(hs @ W_out^T + b_out)
    k_out_mma<<<dim3(OUT_ / 128, M_ROWS / 128), 256, OUT_SMEM>>>(bout, out);
}